// round 2
// baseline (speedup 1.0000x reference)
#include <cuda_runtime.h>
#include <cstddef>
#include <cstdint>

#define Bz 32
#define Tt 4096
#define Uu 512

// 256MB scratch: holds XW = x@w_x + b_h, overwritten in place by H during scan.
__device__ float g_xw[(size_t)Bz * Tt * Uu];

// ---------------------------------------------------------------------------
// Stable tanh: polynomial near 0, exp-based elsewhere (avoids fast-math traps)
// ---------------------------------------------------------------------------
__device__ __forceinline__ float my_tanh(float x) {
    float ax = fabsf(x);
    if (ax < 0.125f) {
        float x2 = x * x;
        return x * (1.f + x2 * (-0.333333333f + x2 * 0.133333333f));
    }
    float e = __expf(2.f * ax);
    float r = 1.f - 2.f / (1.f + e);
    return copysignf(r, x);
}

// ---------------------------------------------------------------------------
// SGEMM with bias: C[M,512] = A[M,512] @ B[512,512] + bias[512]
// 128x128 tile, BK=16, 256 threads, 8x8 per thread. (unchanged from R1)
// ---------------------------------------------------------------------------
__global__ __launch_bounds__(256) void sgemm_bias(
    const float* __restrict__ A, const float* __restrict__ Bm,
    const float* __restrict__ bias, float* __restrict__ C)
{
    __shared__ float As[16][132];
    __shared__ float Bs[16][128];
    const int tid = threadIdx.x;
    const int tx = tid & 15, ty = tid >> 4;
    const size_t row0 = (size_t)blockIdx.y * 128;
    const int col0 = blockIdx.x * 128;

    float acc[8][8];
#pragma unroll
    for (int i = 0; i < 8; i++)
#pragma unroll
        for (int j = 0; j < 8; j++) acc[i][j] = 0.f;

    for (int k0 = 0; k0 < 512; k0 += 16) {
#pragma unroll
        for (int l = 0; l < 2; l++) {
            int f = tid + l * 256;
            int ar = f >> 2, ak = (f & 3) << 2;
            float4 av = *(const float4*)&A[(row0 + ar) * 512 + k0 + ak];
            As[ak + 0][ar] = av.x;
            As[ak + 1][ar] = av.y;
            As[ak + 2][ar] = av.z;
            As[ak + 3][ar] = av.w;
            int br = f >> 5, bc = (f & 31) << 2;
            *(float4*)&Bs[br][bc] =
                *(const float4*)&Bm[(size_t)(k0 + br) * 512 + col0 + bc];
        }
        __syncthreads();
#pragma unroll
        for (int k = 0; k < 16; k++) {
            float a[8], b[8];
            *(float4*)&a[0] = *(const float4*)&As[k][ty * 8];
            *(float4*)&a[4] = *(const float4*)&As[k][ty * 8 + 4];
            *(float4*)&b[0] = *(const float4*)&Bs[k][tx * 8];
            *(float4*)&b[4] = *(const float4*)&Bs[k][tx * 8 + 4];
#pragma unroll
            for (int i = 0; i < 8; i++)
#pragma unroll
                for (int j = 0; j < 8; j++)
                    acc[i][j] = fmaf(a[i], b[j], acc[i][j]);
        }
        __syncthreads();
    }

    float bj[8];
    *(float4*)&bj[0] = *(const float4*)&bias[col0 + tx * 8];
    *(float4*)&bj[4] = *(const float4*)&bias[col0 + tx * 8 + 4];
#pragma unroll
    for (int i = 0; i < 8; i++) {
        size_t r = row0 + ty * 8 + i;
        float4 v0 = make_float4(acc[i][0] + bj[0], acc[i][1] + bj[1],
                                acc[i][2] + bj[2], acc[i][3] + bj[3]);
        float4 v1 = make_float4(acc[i][4] + bj[4], acc[i][5] + bj[5],
                                acc[i][6] + bj[6], acc[i][7] + bj[7]);
        *(float4*)&C[r * 512 + col0 + tx * 8] = v0;
        *(float4*)&C[r * 512 + col0 + tx * 8 + 4] = v1;
    }
}

// ---------------------------------------------------------------------------
// Recurrent scan v2: 16 clusters x 8 CTAs. Cluster g owns batches {2g, 2g+1}.
// CTA rank r owns units [64r, 64r+64). Weights register-resident:
// thread (u = tid>>2, kq = tid&3) holds w_h[kq*128 .. +128)[u0+u] in regs.
// h exchanged via DSMEM scatter + one barrier.cluster per step.
// h layout in SMEM (per buffer): [b][kq][132] (4-float pad per 128 block).
// ---------------------------------------------------------------------------
__global__ void __cluster_dims__(8, 1, 1) __launch_bounds__(256, 1)
rnn_scan2(const float* __restrict__ w_h, const float* __restrict__ h0)
{
    __shared__ float h_s[2 * 1056];   // two buffers of 2*528 floats

    const int tid = threadIdx.x;
    const int u = tid >> 2;           // 0..63
    const int kq = tid & 3;           // 0..3
    const int rank = blockIdx.x & 7;  // cluster_ctarank (1-D cluster)
    const int grp = blockIdx.x >> 3;  // 0..15
    const int b0g = grp * 2;
    const int u_glob = rank * 64 + u;

    // ---- load this thread's w slice into registers (one-time) ----
    float4 wreg[32];
#pragma unroll
    for (int i = 0; i < 32; i++) {
        int d = kq * 128 + i * 4;
        wreg[i].x = __ldg(&w_h[(size_t)(d + 0) * 512 + u_glob]);
        wreg[i].y = __ldg(&w_h[(size_t)(d + 1) * 512 + u_glob]);
        wreg[i].z = __ldg(&w_h[(size_t)(d + 2) * 512 + u_glob]);
        wreg[i].w = __ldg(&w_h[(size_t)(d + 3) * 512 + u_glob]);
    }

    // ---- init h_{-1} into buffer 1 (broadcast h0 over both batches) ----
    for (int i = tid; i < 1024; i += 256) {
        int b = i >> 9, d = i & 511;
        h_s[1056 + b * 528 + (d >> 7) * 132 + (d & 127)] = h0[d];
    }
    __syncthreads();

    const uint32_t hs_addr = (uint32_t)__cvta_generic_to_shared(h_s);

    // writer lanes: kq==0 -> batch 0, kq==1 -> batch 1 of (u_glob)
    const int wb = kq;                         // valid when kq < 2
    const uint32_t scat_off =
        (uint32_t)((wb * 528 + (u_glob >> 7) * 132 + (u_glob & 127)) * 4);

    float xw_cur = 0.f;
    size_t xw_base = 0;
    if (kq < 2) {
        xw_base = (size_t)(b0g + wb) * Tt * Uu + u_glob;
        xw_cur = g_xw[xw_base];                // xw for t = 0
    }

    for (int t = 0; t < Tt; t++) {
        const float4* hb0 = (const float4*)(h_s + ((t + 1) & 1) * 1056 + kq * 132);
        const float4* hb1 = (const float4*)((const float*)hb0 + 528);

        float4 a0 = make_float4(0.f, 0.f, 0.f, 0.f);
        float4 a1 = make_float4(0.f, 0.f, 0.f, 0.f);
#pragma unroll
        for (int c = 0; c < 4; c++) {     // chunked to cap live registers
#pragma unroll
            for (int i = c * 8; i < c * 8 + 8; i++) {
                float4 hv0 = hb0[i];
                float4 hv1 = hb1[i];
                float4 w = wreg[i];
                a0.x = fmaf(w.x, hv0.x, a0.x);
                a0.y = fmaf(w.y, hv0.y, a0.y);
                a0.z = fmaf(w.z, hv0.z, a0.z);
                a0.w = fmaf(w.w, hv0.w, a0.w);
                a1.x = fmaf(w.x, hv1.x, a1.x);
                a1.y = fmaf(w.y, hv1.y, a1.y);
                a1.z = fmaf(w.z, hv1.z, a1.z);
                a1.w = fmaf(w.w, hv1.w, a1.w);
            }
            asm volatile("" ::: "memory");   // scheduling fence: limit load batching
        }

        float s0 = (a0.x + a0.y) + (a0.z + a0.w);
        float s1 = (a1.x + a1.y) + (a1.z + a1.w);
        s0 += __shfl_xor_sync(0xffffffffu, s0, 1);
        s0 += __shfl_xor_sync(0xffffffffu, s0, 2);
        s1 += __shfl_xor_sync(0xffffffffu, s1, 1);
        s1 += __shfl_xor_sync(0xffffffffu, s1, 2);

        float val = 0.f;
        if (kq < 2) {
            float s = (kq == 0) ? s0 : s1;
            val = my_tanh(s + xw_cur);
            // scatter h value to all 8 CTAs of the cluster (incl. self)
            uint32_t loff = hs_addr + (uint32_t)(t & 1) * 4224u + scat_off;
#pragma unroll
            for (int p = 0; p < 8; p++) {
                asm volatile(
                    "{\n\t.reg .u32 ra;\n\t"
                    "mapa.shared::cluster.u32 ra, %0, %1;\n\t"
                    "st.shared::cluster.f32 [ra], %2;\n\t}"
                    :: "r"(loff), "r"(p), "f"(val) : "memory");
            }
        }

        // release our DSMEM stores; overlap global work with barrier wait
        asm volatile("barrier.cluster.arrive.aligned;" ::: "memory");
        if (kq < 2) {
            g_xw[xw_base + (size_t)t * Uu] = val;          // persist H (in place)
            if (t + 1 < Tt)
                xw_cur = g_xw[xw_base + (size_t)(t + 1) * Uu];  // prefetch next xw
        }
        asm volatile("barrier.cluster.wait.aligned;" ::: "memory");
    }
}

// ---------------------------------------------------------------------------
__global__ void copy_hfinal(float* __restrict__ out) {
    int i = blockIdx.x * 256 + threadIdx.x;
    if (i < Bz * Uu) {
        int b = i >> 9, u = i & 511;
        out[(size_t)Bz * Tt * Uu + i] =
            g_xw[((size_t)b * Tt + (Tt - 1)) * Uu + u];
    }
}

// ---------------------------------------------------------------------------
extern "C" void kernel_launch(void* const* d_in, const int* in_sizes, int n_in,
                              void* d_out, int out_size) {
    const float* x   = (const float*)d_in[0];
    const float* w_h = (const float*)d_in[1];
    const float* w_x = (const float*)d_in[2];
    const float* w_y = (const float*)d_in[3];
    const float* b_h = (const float*)d_in[4];
    const float* b_y = (const float*)d_in[5];
    const float* h0  = (const float*)d_in[6];
    float* out = (float*)d_out;

    float* xw = nullptr;
    cudaGetSymbolAddress((void**)&xw, g_xw);

    dim3 gg(4, 1024);  // N-tiles x M-tiles for M=131072, N=512

    // Phase 1: XW = x @ w_x + b_h
    sgemm_bias<<<gg, 256>>>(x, w_x, b_h, xw);
    // Phase 2: sequential scan, H overwrites XW in place (128 CTAs, 16 clusters)
    rnn_scan2<<<128, 256>>>(w_h, h0);
    // Phase 3: Y = H @ w_y + b_y  -> d_out[0 .. B*T*U)
    sgemm_bias<<<gg, 256>>>(xw, w_y, b_y, out);
    // h_final = H[:, T-1, :]      -> d_out[B*T*U ..)
    copy_hfinal<<<64, 256>>>(out);
}

// round 4
// speedup vs baseline: 1.5854x; 1.5854x over previous
#include <cuda_runtime.h>
#include <cstddef>
#include <cstdint>

#define Bz 32
#define Tt 4096
#define Uu 512

// 256MB scratch: holds XW = x@w_x + b_h, overwritten in place by H during scan.
__device__ float g_xw[(size_t)Bz * Tt * Uu];
// per-CTA step flags: flag[grp*128 + cig*8] (32B apart), monotonically = t+1
__device__ unsigned int g_flag[8 * 128];

// ---------------------------------------------------------------------------
__device__ __forceinline__ float my_tanh(float x) {
    float ax = fabsf(x);
    if (ax < 0.125f) {
        float x2 = x * x;
        return x * (1.f + x2 * (-0.333333333f + x2 * 0.133333333f));
    }
    float e = __expf(2.f * ax);
    float r = 1.f - 2.f / (1.f + e);
    return copysignf(r, x);
}

// ---------------------------------------------------------------------------
// SGEMM with bias: C[M,512] = A[M,512] @ B[512,512] + bias[512]
// 128x128 tile, BK=16, 256 threads, 8x8 per thread.
// Optional: flag reset (stream-ordered ahead of the scan kernel).
// ---------------------------------------------------------------------------
__global__ __launch_bounds__(256) void sgemm_bias(
    const float* __restrict__ A, const float* __restrict__ Bm,
    const float* __restrict__ bias, float* __restrict__ C,
    unsigned int* __restrict__ rflags)
{
    __shared__ float As[16][132];
    __shared__ float Bs[16][128];
    const int tid = threadIdx.x;
    const int tx = tid & 15, ty = tid >> 4;
    const size_t row0 = (size_t)blockIdx.y * 128;
    const int col0 = blockIdx.x * 128;

    if (rflags && blockIdx.x == 0 && blockIdx.y == 0 && tid < 128)
        rflags[(tid >> 4) * 128 + (tid & 15) * 8] = 0u;

    float acc[8][8];
#pragma unroll
    for (int i = 0; i < 8; i++)
#pragma unroll
        for (int j = 0; j < 8; j++) acc[i][j] = 0.f;

    for (int k0 = 0; k0 < 512; k0 += 16) {
#pragma unroll
        for (int l = 0; l < 2; l++) {
            int f = tid + l * 256;
            int ar = f >> 2, ak = (f & 3) << 2;
            float4 av = *(const float4*)&A[(row0 + ar) * 512 + k0 + ak];
            As[ak + 0][ar] = av.x;
            As[ak + 1][ar] = av.y;
            As[ak + 2][ar] = av.z;
            As[ak + 3][ar] = av.w;
            int br = f >> 5, bc = (f & 31) << 2;
            *(float4*)&Bs[br][bc] =
                *(const float4*)&Bm[(size_t)(k0 + br) * 512 + col0 + bc];
        }
        __syncthreads();
#pragma unroll
        for (int k = 0; k < 16; k++) {
            float a[8], b[8];
            *(float4*)&a[0] = *(const float4*)&As[k][ty * 8];
            *(float4*)&a[4] = *(const float4*)&As[k][ty * 8 + 4];
            *(float4*)&b[0] = *(const float4*)&Bs[k][tx * 8];
            *(float4*)&b[4] = *(const float4*)&Bs[k][tx * 8 + 4];
#pragma unroll
            for (int i = 0; i < 8; i++)
#pragma unroll
                for (int j = 0; j < 8; j++)
                    acc[i][j] = fmaf(a[i], b[j], acc[i][j]);
        }
        __syncthreads();
    }

    float bj[8];
    *(float4*)&bj[0] = *(const float4*)&bias[col0 + tx * 8];
    *(float4*)&bj[4] = *(const float4*)&bias[col0 + tx * 8 + 4];
#pragma unroll
    for (int i = 0; i < 8; i++) {
        size_t r = row0 + ty * 8 + i;
        float4 v0 = make_float4(acc[i][0] + bj[0], acc[i][1] + bj[1],
                                acc[i][2] + bj[2], acc[i][3] + bj[3]);
        float4 v1 = make_float4(acc[i][4] + bj[4], acc[i][5] + bj[5],
                                acc[i][6] + bj[6], acc[i][7] + bj[7]);
        *(float4*)&C[r * 512 + col0 + tx * 8] = v0;
        *(float4*)&C[r * 512 + col0 + tx * 8 + 4] = v1;
    }
}

// ---------------------------------------------------------------------------
// Recurrent scan v3. 8 groups x 16 CTAs. Group g owns batches [4g, 4g+4).
// CTA c-in-group owns units [32c, 32c+32), w_h slice (512x32) in SMEM.
// Sync: per-CTA release flag + warp-0 acquire ballot poll. No fences/atomics.
// ---------------------------------------------------------------------------
__global__ __launch_bounds__(256) void rnn_scan3(const float* __restrict__ w_h,
                                                 const float* __restrict__ h0)
{
    extern __shared__ float smem[];
    float* w_s  = smem;                  // 512*32 = 16384 floats (64KB)
    float* h_s  = smem + 16384;          // 4*512  = 2048 floats
    float* psum = smem + 16384 + 2048;   // 8*128  = 1024 floats

    const int tid = threadIdx.x;
    const int grp = blockIdx.x >> 4;     // 0..7
    const int cig = blockIdx.x & 15;     // 0..15
    const int b0 = grp << 2;
    const int u0 = cig << 5;

    for (int i = tid; i < 16384; i += 256) {
        int d = i >> 5, j = i & 31;
        w_s[i] = w_h[d * 512 + u0 + j];
    }

    const int ut   = tid & 7;
    const int dcw  = tid >> 3;
    const int lane = tid & 31;
    const int warp = tid >> 5;
    const int d0q  = dcw << 2;
    const float4* w_s4 = (const float4*)w_s;
    const float4* h_s4 = (const float4*)h_s;

    unsigned int* myflag = &g_flag[grp * 128 + cig * 8];
    unsigned int* fbase  = &g_flag[grp * 128];

    // own output slot for the final-reduce stage (tid < 128)
    size_t oidx = 0;
    float xw_pf = 0.f;
    if (tid < 128) {
        oidx = ((size_t)(b0 + (tid & 3)) * Tt) * Uu + u0 + (tid >> 2);
        xw_pf = __ldcg(&g_xw[oidx]);           // xw for t=0, L2-only (no L1 line)
    }

    // h_{-1} = h0 broadcast over 4 batches
    for (int i = tid; i < 2048; i += 256) h_s[i] = h0[i & 511];
    __syncthreads();

    for (int t = 0; t < Tt; t++) {
        // ---- partial dot products: 4 units x 4 batches over 16 d ----
        float acc[16];
#pragma unroll
        for (int z = 0; z < 16; z++) acc[z] = 0.f;
#pragma unroll
        for (int i = 0; i < 4; i++) {
            float4 hv[4];
            hv[0] = h_s4[d0q + i];
            hv[1] = h_s4[128 + d0q + i];
            hv[2] = h_s4[256 + d0q + i];
            hv[3] = h_s4[384 + d0q + i];
#pragma unroll
            for (int j = 0; j < 4; j++) {
                float4 wv = w_s4[((d0q + i) * 4 + j) * 8 + ut];
                const float w0 = wv.x, w1 = wv.y, w2 = wv.z, w3 = wv.w;
#pragma unroll
                for (int b = 0; b < 4; b++) {
                    float hb = ((const float*)&hv[b])[j];
                    acc[b * 4 + 0] = fmaf(w0, hb, acc[b * 4 + 0]);
                    acc[b * 4 + 1] = fmaf(w1, hb, acc[b * 4 + 1]);
                    acc[b * 4 + 2] = fmaf(w2, hb, acc[b * 4 + 2]);
                    acc[b * 4 + 3] = fmaf(w3, hb, acc[b * 4 + 3]);
                }
            }
        }

        // ---- warp reduce over the 4 d-chunks (lane bits 3,4) ----
#pragma unroll
        for (int z = 0; z < 16; z++) {
            acc[z] += __shfl_xor_sync(0xffffffffu, acc[z], 8);
            acc[z] += __shfl_xor_sync(0xffffffffu, acc[z], 16);
        }
        if (lane < 8) {
#pragma unroll
            for (int uj = 0; uj < 4; uj++)
#pragma unroll
                for (int b = 0; b < 4; b++)
                    psum[warp * 128 + ((ut * 4 + uj) << 2) + b] = acc[b * 4 + uj];
        }
        __syncthreads();

        // ---- final reduce over 8 warps, tanh, persist h_t ----
        if (tid < 128) {
            float s = 0.f;
#pragma unroll
            for (int w = 0; w < 8; w++) s += psum[w * 128 + tid];
            float val = my_tanh(s + xw_pf);
            g_xw[oidx + (size_t)t * Uu] = val;
            if (t + 1 < Tt)   // prefetch next xw (L2-only) under the barrier
                xw_pf = __ldcg(&g_xw[oidx + (size_t)(t + 1) * Uu]);
        }
        __syncthreads();   // all h stores of this CTA issued before release

        // ---- release our flag, poll the 16 flags of the group ----
        if (tid == 0)
            asm volatile("st.release.gpu.global.u32 [%0], %1;"
                         :: "l"(myflag), "r"((unsigned)(t + 1)) : "memory");
        if (warp == 0) {
            unsigned int* faddr = fbase + (lane & 15) * 8;
            unsigned int v;
            do {
                asm volatile("ld.acquire.gpu.global.u32 %0, [%1];"
                             : "=r"(v) : "l"(faddr));
            } while (__ballot_sync(0xffffffffu, v >= (unsigned)(t + 1))
                     != 0xffffffffu);
        }
        __syncthreads();

        // ---- load h_t (written by all 16 CTAs of the group) ----
        if (t + 1 < Tt) {
            for (int i = tid; i < 512; i += 256) {
                int b = i >> 7, d4 = i & 127;
                ((float4*)h_s)[i] =
                    *((const float4*)&g_xw[((size_t)(b0 + b) * Tt + t) * Uu] + d4);
            }
            __syncthreads();
        }
    }
}

// ---------------------------------------------------------------------------
// h_final = H[:, T-1, :]  (H itself, NOT its w_y projection)
__global__ void copy_hfinal(float* __restrict__ out) {
    int i = blockIdx.x * 256 + threadIdx.x;
    if (i < Bz * Uu) {
        int b = i >> 9, u = i & 511;
        out[(size_t)Bz * Tt * Uu + i] =
            g_xw[((size_t)b * Tt + (Tt - 1)) * Uu + u];
    }
}

// ---------------------------------------------------------------------------
extern "C" void kernel_launch(void* const* d_in, const int* in_sizes, int n_in,
                              void* d_out, int out_size) {
    const float* x   = (const float*)d_in[0];
    const float* w_h = (const float*)d_in[1];
    const float* w_x = (const float*)d_in[2];
    const float* w_y = (const float*)d_in[3];
    const float* b_h = (const float*)d_in[4];
    const float* b_y = (const float*)d_in[5];
    const float* h0  = (const float*)d_in[6];
    float* out = (float*)d_out;

    float* xw = nullptr;
    unsigned int* flags = nullptr;
    cudaGetSymbolAddress((void**)&xw, g_xw);
    cudaGetSymbolAddress((void**)&flags, g_flag);
    cudaFuncSetAttribute(rnn_scan3, cudaFuncAttributeMaxDynamicSharedMemorySize,
                         (16384 + 2048 + 1024) * 4);

    dim3 gg(4, 1024);

    // Phase 1: XW = x @ w_x + b_h  (also resets scan flags)
    sgemm_bias<<<gg, 256>>>(x, w_x, b_h, xw, flags);
    // Phase 2: sequential scan, H overwrites XW in place
    rnn_scan3<<<128, 256, (16384 + 2048 + 1024) * 4>>>(w_h, h0);
    // Phase 3: Y = H @ w_y + b_y
    sgemm_bias<<<gg, 256>>>(xw, w_y, b_y, out, nullptr);
    // h_final = H[:, T-1, :]
    copy_hfinal<<<64, 256>>>(out);
}